// round 7
// baseline (speedup 1.0000x reference)
#include <cuda_runtime.h>
#include <cstdint>
#include <cstddef>

#define S_LEN 8192
#define HID   768
#define GATE4 3072   // 4*H
#define E_DIM 300    // !! embedding dim is 300, not 768
#define V_SZ  100000

// ---------------- scratch (device globals; no runtime allocation) -----------
__device__ float g_gates_f[(size_t)S_LEN * GATE4];   // ~100MB per direction
__device__ float g_gates_b[(size_t)S_LEN * GATE4];
__device__ float g_h[2][2][HID];                     // [dir][parity][H]
__device__ int   g_cnt[2];                           // per-direction arrival counters

// ---------------- init: reset state each launch -----------------------------
__global__ void init_kernel() {
    int t = threadIdx.x;
    if (t < 2) g_cnt[t] = 0;
    for (int i = t; i < 2 * 2 * HID; i += blockDim.x)
        ((float*)g_h)[i] = 0.f;
}

// ---------------- fused gather + input-projection SGEMM ---------------------
// out[s][n] = emb[idx[s]] . W[n] + (b_ih[n]+b_hh[n]) for one direction.
// A: (8192, 300) gathered rows of emb. B: W (3072, 300). K = 300 = 8*37 + 4.
// grid (24, 64): bx = N tile (128 of 3072), by = M tile (128 of 8192)
__global__ __launch_bounds__(256) void gemm_gates(
    const int*   __restrict__ idx, int n_idx,
    const float* __restrict__ emb,
    const float* __restrict__ W,
    const float* __restrict__ bih, const float* __restrict__ bhh,
    int dir)
{
    __shared__ float As[8][132];
    __shared__ float Bs[8][132];
    __shared__ int   sidx[128];

    float* __restrict__ outg = dir ? g_gates_b : g_gates_f;

    const int tid = threadIdx.x;
    const int m0 = blockIdx.y * 128;
    const int n0 = blockIdx.x * 128;

    if (tid < 128) {
        int ii = m0 + tid;
        if (ii >= n_idx) ii = n_idx - 1;
        if (ii < 0) ii = 0;
        int v = idx[ii];
        v = v < 0 ? 0 : (v >= V_SZ ? V_SZ - 1 : v);
        sidx[tid] = v;
    }
    __syncthreads();

    const int arow = tid >> 1;          // 0..127
    const int acol = (tid & 1) * 4;     // 0 or 4
    const float* arow_p = emb + (size_t)sidx[arow] * E_DIM;   // row stride 300
    const float* brow_p = W   + (size_t)(n0 + arow) * E_DIM;  // row stride 300

    const int tx = tid & 15;            // N micro
    const int ty = tid >> 4;            // M micro

    float acc[8][8];
    #pragma unroll
    for (int i = 0; i < 8; i++)
        #pragma unroll
        for (int j = 0; j < 8; j++) acc[i][j] = 0.f;

    for (int k0 = 0; k0 < E_DIM; k0 += 8) {           // 38 tiles, last partial (4)
        #pragma unroll
        for (int q = 0; q < 4; q++) {
            const int kk = k0 + acol + q;
            const bool in = (kk < E_DIM);
            As[acol + q][arow] = in ? arow_p[kk] : 0.f;   // scalar LDG, guarded
            Bs[acol + q][arow] = in ? brow_p[kk] : 0.f;
        }
        __syncthreads();

        #pragma unroll
        for (int k = 0; k < 8; k++) {
            float a[8], b[8];
            #pragma unroll
            for (int i = 0; i < 8; i++) a[i] = As[k][ty * 8 + i];
            #pragma unroll
            for (int j = 0; j < 8; j++) b[j] = Bs[k][tx * 8 + j];
            #pragma unroll
            for (int i = 0; i < 8; i++)
                #pragma unroll
                for (int j = 0; j < 8; j++)
                    acc[i][j] = fmaf(a[i], b[j], acc[i][j]);
        }
        __syncthreads();
    }

    float bias[8];
    #pragma unroll
    for (int j = 0; j < 8; j++) {
        const int n = n0 + tx * 8 + j;            // <= 3071
        bias[j] = bih[n] + bhh[n];
    }
    #pragma unroll
    for (int i = 0; i < 8; i++) {
        const size_t row = (size_t)(m0 + ty * 8 + i);
        float* op = outg + row * GATE4 + n0 + tx * 8;
        #pragma unroll
        for (int j = 0; j < 8; j++)
            op[j] = acc[i][j] + bias[j];
    }
}

// ---------------- activations ------------------------------------------------
__device__ __forceinline__ float sigf(float x) {
    return __fdividef(1.f, 1.f + __expf(-x));
}
__device__ __forceinline__ float tanhf_fast(float x) {
    return 1.f - __fdividef(2.f, __expf(2.f * x) + 1.f);
}

// ---------------- persistent recurrence --------------------------------------
// 128 CTAs: [0,64) forward dir, [64,128) backward dir. Each CTA owns 12 hidden
// units = 48 gate rows of W_hh (3072x768), register-resident.
__global__ __launch_bounds__(256, 1) void lstm_rec(
    const float* __restrict__ Whhf, const float* __restrict__ Whhb)
{
    const int cta = blockIdx.x;
    const int d   = cta >> 6;
    const int cc  = cta & 63;
    const float* __restrict__ Whh   = d ? Whhb      : Whhf;
    const float* __restrict__ gbase = d ? g_gates_b : g_gates_f;
    const int tid = threadIdx.x;
    const int w = tid >> 5;
    const int l = tid & 31;
    const int u0 = cc * 12;

    // local row rr in [0,48): gate = rr/12, unit = u0 + rr%12
    float wreg[6][24];
    #pragma unroll
    for (int r = 0; r < 6; r++) {
        const int rr = w * 6 + r;
        const int grow = (rr / 12) * HID + u0 + (rr % 12);   // <= 3071
        const float* wp = Whh + (size_t)grow * HID + l;
        #pragma unroll
        for (int j = 0; j < 24; j++) wreg[r][j] = wp[32 * j];
    }

    __shared__ float hsh[HID];
    __shared__ float rowsum[48];
    float cstate = 0.f;                 // live in threads 0..11
    volatile int* cntv = &g_cnt[d];
    float* hbuf0 = g_h[d][0];
    float* hbuf1 = g_h[d][1];

    for (int t = 1; t <= S_LEN; t++) {
        // prefetch this step's precomputed input gates (independent of h)
        float gi = 0.f, gf2 = 0.f, gg = 0.f, go = 0.f;
        if (tid < 12) {
            const float* gp = gbase + (size_t)(t - 1) * GATE4 + u0 + tid;
            gi  = gp[0];
            gf2 = gp[HID];
            gg  = gp[2 * HID];
            go  = gp[3 * HID];
        }

        // wait until h_{t-1} is fully published by all 64 CTAs of this dir
        if (t > 1) {
            if (tid == 0) {
                const int target = 64 * (t - 1);
                while (*cntv < target) __nanosleep(32);
                __threadfence();          // acquire: order h reads after flag
            }
            __syncthreads();
        }

        // stage h_{t-1} into shared memory (one pass for the whole CTA)
        const float* hsrc = ((t - 1) & 1) ? hbuf1 : hbuf0;
        #pragma unroll
        for (int j = 0; j < HID / 256; j++)
            hsh[tid + 256 * j] = __ldcg(hsrc + tid + 256 * j);
        __syncthreads();

        float acc[6] = {0.f, 0.f, 0.f, 0.f, 0.f, 0.f};
        #pragma unroll
        for (int j = 0; j < 24; j++) {
            const float hv = hsh[l + 32 * j];
            #pragma unroll
            for (int r = 0; r < 6; r++)
                acc[r] = fmaf(wreg[r][j], hv, acc[r]);
        }

        // warp butterfly reduce (6 independent trees)
        #pragma unroll
        for (int sh = 16; sh > 0; sh >>= 1)
            #pragma unroll
            for (int r = 0; r < 6; r++)
                acc[r] += __shfl_xor_sync(0xffffffffu, acc[r], sh);

        if (l == 0) {
            #pragma unroll
            for (int r = 0; r < 6; r++) rowsum[w * 6 + r] = acc[r];
        }
        __syncthreads();

        if (tid < 12) {
            const float xi = rowsum[tid]      + gi;
            const float xf = rowsum[12 + tid] + gf2;
            const float xg = rowsum[24 + tid] + gg;
            const float xo = rowsum[36 + tid] + go;
            const float ig = sigf(xi);
            const float fg = sigf(xf);
            const float og = sigf(xo);
            const float gt = tanhf_fast(xg);
            cstate = fmaf(fg, cstate, ig * gt);
            const float hv = og * tanhf_fast(cstate);
            float* hdst = (t & 1) ? hbuf1 : hbuf0;
            hdst[u0 + tid] = hv;
        }
        __syncthreads();             // h writes done + smem reuse ordering
        if (tid == 0) {
            __threadfence();         // publish h slice before arriving
            atomicAdd(&g_cnt[d], 1);
        }
    }
}

// ---------------- final tag projection ---------------------------------------
__global__ void tag_kernel(const float* __restrict__ Wtag,
                           const float* __restrict__ btag,
                           float* __restrict__ out)
{
    const int w = threadIdx.x >> 5;
    const int l = threadIdx.x & 31;
    if (w >= 20) return;
    // final h_T (t=8192) landed in parity 0
    const float* hf = g_h[0][0];
    const float* hb = g_h[1][0];
    float s = 0.f;
    #pragma unroll
    for (int j = 0; j < 48; j++) {
        int k = l + 32 * j;            // 0..1535
        float hv = (k < HID) ? hf[k] : hb[k - HID];
        s = fmaf(Wtag[w * (2 * HID) + k], hv, s);
    }
    #pragma unroll
    for (int sh = 16; sh > 0; sh >>= 1)
        s += __shfl_xor_sync(0xffffffffu, s, sh);
    if (l == 0) out[w] = s + btag[w];
}

// ---------------- launch ------------------------------------------------------
extern "C" void kernel_launch(void* const* d_in, const int* in_sizes, int n_in,
                              void* d_out, int out_size)
{
    // Map inputs by element count (unique per tensor group with E=300):
    //   inpu 8192 | emb 30,000,000 | W_ih 921,600 x2 | W_hh 2,359,296 x2
    //   biases 3072 x4 | W_tag 30,720 | b_tag 20
    int i_inpu = -1, i_emb = -1, i_wt = -1, i_bt = -1;
    int iWih[2] = {-1, -1}, iWhh[2] = {-1, -1}, iB[4] = {-1, -1, -1, -1};
    int nWih = 0, nWhh = 0, nB = 0;
    for (int i = 0; i < n_in; i++) {
        long s = in_sizes[i];
        if      (s == 8192     && i_inpu < 0) i_inpu = i;
        else if (s == 30000000 && i_emb  < 0) i_emb  = i;
        else if (s == 921600   && nWih < 2)   iWih[nWih++] = i;
        else if (s == 2359296  && nWhh < 2)   iWhh[nWhh++] = i;
        else if (s == 3072     && nB < 4)     iB[nB++] = i;
        else if (s == 30720    && i_wt  < 0)  i_wt  = i;
        else if (s == 20       && i_bt  < 0)  i_bt  = i;
    }
    const bool ok = i_inpu >= 0 && i_emb >= 0 && nWih == 2 && nWhh == 2 &&
                    nB == 4 && i_wt >= 0 && i_bt >= 0;
    if (!ok) {
        // positional fallback (reference signature order), clamped so a bad
        // mapping yields wrong numbers, never a wild pointer
        const int m = n_in - 1;
        #define CLMP(x) ((x) < 0 ? 0 : ((x) > m ? m : (x)))
        i_inpu = CLMP(0); i_emb = CLMP(1);
        iWih[0] = CLMP(2); iWhh[0] = CLMP(3);
        iB[0] = CLMP(4); iB[1] = CLMP(5);
        iWih[1] = CLMP(6); iWhh[1] = CLMP(7);
        iB[2] = CLMP(8); iB[3] = CLMP(9);
        i_wt = CLMP(10); i_bt = CLMP(11);
        #undef CLMP
    }

    const int*   inpu = (const int*)  d_in[i_inpu];
    const float* emb  = (const float*)d_in[i_emb];
    const float* Wihf = (const float*)d_in[iWih[0]];
    const float* Whhf = (const float*)d_in[iWhh[0]];
    const float* Wihb = (const float*)d_in[iWih[1]];
    const float* Whhb = (const float*)d_in[iWhh[1]];
    const float* bihf = (const float*)d_in[iB[0]];
    const float* bhhf = (const float*)d_in[iB[1]];
    const float* bihb = (const float*)d_in[iB[2]];
    const float* bhhb = (const float*)d_in[iB[3]];
    const float* Wtag = (const float*)d_in[i_wt];
    const float* btag = (const float*)d_in[i_bt];
    float* out = (float*)d_out;

    const int n_idx = in_sizes[i_inpu];

    init_kernel<<<1, 256>>>();
    gemm_gates<<<dim3(24, 64), 256>>>(inpu, n_idx, emb, Wihf, bihf, bhhf, 0);
    gemm_gates<<<dim3(24, 64), 256>>>(inpu, n_idx, emb, Wihb, bihb, bhhb, 1);
    lstm_rec<<<128, 256>>>(Whhf, Whhb);
    tag_kernel<<<1, 640>>>(Wtag, btag, out);
}